// round 13
// baseline (speedup 1.0000x reference)
#include <cuda_runtime.h>
#include <cuda_fp16.h>
#include <cstdint>

#define K3          27
#define PAIRS_PER_K 131072
#define N_VOX       262144
#define C_IN        32
#define C_OUT       32
#define M_TOTAL     (K3 * PAIRS_PER_K)

#define TILE        128                     // pairs per MMA tile (8 warps x 16)
#define NT          16                      // tiles per block (same k)
#define TPB         256
#define TILES_PER_K (PAIRS_PER_K / TILE)    // 1024 (divisible by NT)
#define GRID        (M_TOTAL / TILE / NT)   // 1728
#define RSH         40                      // A row stride in halves (80B)
#define RSD         40                      // D row stride in floats (160B)

// 16MB fp16 copy of in_feature (static device scratch — no allocation).
__device__ __half2 g_hfeat[N_VOX * C_IN / 2];

// ---------------------------------------------------------------------------
// Kernel 1 (fused): bias-init of d_out AND f32->fp16 convert of in_feature.
// Each thread: 2 bias float4 writes + 8-float convert. 4096 blocks x 256.
// ---------------------------------------------------------------------------
__global__ void prolog_kernel(float4* __restrict__ out,
                              const float4* __restrict__ bias4,
                              const float4* __restrict__ in4) {
    const int t = blockIdx.x * blockDim.x + threadIdx.x;   // < N_VOX*4
    const float4 a = in4[2 * t];
    const float4 b = in4[2 * t + 1];
    out[2 * t]     = bias4[(2 * t) & 7];
    out[2 * t + 1] = bias4[(2 * t + 1) & 7];
    __half2* dst = g_hfeat + 4 * t;
    dst[0] = __floats2half2_rn(a.x, a.y);
    dst[1] = __floats2half2_rn(a.z, a.w);
    dst[2] = __floats2half2_rn(b.x, b.y);
    dst[3] = __floats2half2_rn(b.z, b.w);
}

__device__ __forceinline__ uint32_t pack_h2(float lo, float hi) {
    __half2 h = __floats2half2_rn(lo, hi);
    return *reinterpret_cast<uint32_t*>(&h);
}

// ---------------------------------------------------------------------------
// Kernel 2: cp.async fp16 gather (double buffer) -> ldmatrix -> fp16
// mma.sync (m16n8k16, B register-resident) -> D staged to smem (RSD=40,
// conflict-free) -> line-coalesced red.global.add.v4 scatter.
// Dst indices hoisted above the MMA chain to hide their LDG latency.
// ---------------------------------------------------------------------------
__global__ void __launch_bounds__(TPB, 4)
conv_mma_kernel(const float* __restrict__ kernel_w,     // [K3][32][32]
                const int*   __restrict__ nbmap,        // [M][2] (src,dst)
                float*       __restrict__ out)          // [N_VOX][32]
{
    __shared__ __align__(16) __half As[2][TILE * RSH];  // 2 x 10240B
    __shared__ __align__(16) float  Ds[TILE * RSD];     // 20480B

    const int tid  = threadIdx.x;
    const int wid  = tid >> 5;
    const int lane = tid & 31;

    const int tile0 = blockIdx.x * NT;
    const int k     = tile0 / TILES_PER_K;

    // ---- ALL B fragments in registers (fp16, loaded once per block) ----
    uint32_t Breg[4][2][2];
    {
        const float* wk = kernel_w + (size_t)k * (C_IN * C_OUT);
        const int bk = 2 * (lane & 3), bn = lane >> 2;
#pragma unroll
        for (int j = 0; j < 4; j++)
#pragma unroll
            for (int s = 0; s < 2; s++) {
                const int kb = 16 * s + bk;
                Breg[j][s][0] = pack_h2(wk[(kb    ) * C_OUT + 8 * j + bn],
                                        wk[(kb + 1) * C_OUT + 8 * j + bn]);
                Breg[j][s][1] = pack_h2(wk[(kb + 8) * C_OUT + 8 * j + bn],
                                        wk[(kb + 9) * C_OUT + 8 * j + bn]);
            }
    }

    const __half* hf = reinterpret_cast<const __half*>(g_hfeat);

    // ---- gather tile t into buffer buf: 512 x cp.async.cg 16B ----
    auto gather = [&](int t, int buf) {
        const size_t pbase = (size_t)(tile0 + t) * TILE;
#pragma unroll
        for (int jj = 0; jj < 2; jj++) {
            const int idx = tid + TPB * jj;          // 0..511
            const int ch  = (idx >> 3) & 3;          // 16B chunk in 64B row
            const int row = (idx & 7) + 8 * (idx >> 5);
            const int v   = nbmap[2 * (pbase + row)];
            const uint32_t dst = (uint32_t)__cvta_generic_to_shared(
                &As[buf][row * RSH + ch * 8]);
            asm volatile("cp.async.cg.shared.global [%0], [%1], 16;"
                         :: "r"(dst), "l"(hf + (size_t)v * C_IN + ch * 8));
        }
        asm volatile("cp.async.commit_group;" ::: "memory");
    };

    gather(0, 0);

    const int ar = lane >> 2;                       // frag row-in-8
    const int ac = lane & 3;                        // frag col-pair
    const int lm_row = 16 * wid + (lane & 15);
    const int lm_off = (lane >> 4) * 8;             // halves
    const int sc_row = 16 * wid + (lane >> 3);      // scatter row base
    const int chunk  = lane & 7;                    // scatter 16B chunk

    for (int t = 0; t < NT; t++) {
        const int buf = t & 1;
        asm volatile("cp.async.wait_group 0;" ::: "memory");
        __syncthreads();                            // A(t) ready; Ds free

        if (t + 1 < NT) gather(t + 1, buf ^ 1);     // overlap with compute

        // Hoist destination indices (LDG latency hidden under MMA chain).
        const size_t pbase = (size_t)(tile0 + t) * TILE;
        int ydst[4];
#pragma unroll
        for (int ii = 0; ii < 4; ii++)
            ydst[ii] = nbmap[2 * (pbase + sc_row + 4 * ii) + 1];

        // A fragments via 2 x ldmatrix.x4 (one per k16 step).
        uint32_t A[2][4];
        const uint32_t abase = (uint32_t)__cvta_generic_to_shared(
            &As[buf][lm_row * RSH + lm_off]);
#pragma unroll
        for (int s = 0; s < 2; s++) {
            asm volatile("ldmatrix.sync.aligned.m8n8.x4.shared.b16 "
                         "{%0,%1,%2,%3}, [%4];"
                         : "=r"(A[s][0]), "=r"(A[s][1]),
                           "=r"(A[s][2]), "=r"(A[s][3])
                         : "r"(abase + 32 * s));    // +16 halves per k-step
        }

#pragma unroll
        for (int j = 0; j < 4; j++) {
            float D0 = 0.f, D1 = 0.f, D2 = 0.f, D3 = 0.f;
#pragma unroll
            for (int s = 0; s < 2; s++) {
                asm volatile(
                    "mma.sync.aligned.m16n8k16.row.col.f32.f16.f16.f32 "
                    "{%0,%1,%2,%3}, {%4,%5,%6,%7}, {%8,%9}, {%0,%1,%2,%3};"
                    : "+f"(D0), "+f"(D1), "+f"(D2), "+f"(D3)
                    : "r"(A[s][0]), "r"(A[s][1]), "r"(A[s][2]), "r"(A[s][3]),
                      "r"(Breg[j][s][0]), "r"(Breg[j][s][1]));
            }
            // Stage D into Ds (warp-private rows; RSD=40 -> conflict-free).
            *reinterpret_cast<float2*>(
                &Ds[(16 * wid + ar)     * RSD + 2 * ac + 8 * j]) =
                make_float2(D0, D1);
            *reinterpret_cast<float2*>(
                &Ds[(16 * wid + ar + 8) * RSD + 2 * ac + 8 * j]) =
                make_float2(D2, D3);
        }
        __syncwarp();

        // Line-coalesced scatter: lanes 0-7 cover one full 128B output row.
#pragma unroll
        for (int ii = 0; ii < 4; ii++) {
            const float4 v = *reinterpret_cast<const float4*>(
                &Ds[(sc_row + 4 * ii) * RSD + chunk * 4]);
            asm volatile("red.global.add.v4.f32 [%0], {%1,%2,%3,%4};"
                         :: "l"(out + (size_t)ydst[ii] * C_OUT + chunk * 4),
                            "f"(v.x), "f"(v.y), "f"(v.z), "f"(v.w)
                         : "memory");
        }
        __syncwarp();   // Ds reads done before next tile overwrites
    }
}

// ---------------------------------------------------------------------------
// Inputs (metadata order): in_feature f32[N_VOX,32], kernel f32[27,32,32],
// bias f32[32], nbmap i32[M,2], nbsizes i32[27]. Output f32[N_VOX,32].
// ---------------------------------------------------------------------------
extern "C" void kernel_launch(void* const* d_in, const int* in_sizes, int n_in,
                              void* d_out, int out_size) {
    const float4* in4      = (const float4*)d_in[0];
    const float*  kernel_w = (const float*)d_in[1];
    const float4* bias4    = (const float4*)d_in[2];
    const int*    nbmap    = (const int*)d_in[3];
    float*        out      = (float*)d_out;

    prolog_kernel<<<N_VOX * 4 / 256, 256>>>((float4*)out, bias4, in4);
    conv_mma_kernel<<<GRID, TPB>>>(kernel_w, nbmap, out);
}

// round 14
// speedup vs baseline: 1.0637x; 1.0637x over previous
#include <cuda_runtime.h>
#include <cuda_fp16.h>
#include <cstdint>

#define K3          27
#define PAIRS_PER_K 131072
#define N_VOX       262144
#define C_IN        32
#define C_OUT       32
#define M_TOTAL     (K3 * PAIRS_PER_K)

#define TILE        128                     // pairs per MMA tile (8 warps x 16)
#define NT          8                       // tiles per block (same k)
#define TPB         256
#define TILES_PER_K (PAIRS_PER_K / TILE)    // 1024 (divisible by NT)
#define GRID        (M_TOTAL / TILE / NT)   // 3456
#define RSH         40                      // A row stride in halves (80B)
#define RSD         40                      // D row stride in floats (160B):
                                            // 8ar+2ac banks -> conflict-free STS.64

// 16MB fp16 copy of in_feature (static device scratch — no allocation).
__device__ __half2 g_hfeat[N_VOX * C_IN / 2];

// ---------------------------------------------------------------------------
// Kernel 1 (fused): bias-init of d_out AND f32->fp16 convert of in_feature.
// Independent streams overlapped in one launch. 8192 blocks x 256.
// ---------------------------------------------------------------------------
__global__ void prolog_kernel(float4* __restrict__ out,
                              const float4* __restrict__ bias4,
                              const float4* __restrict__ in4) {
    const int t = blockIdx.x * blockDim.x + threadIdx.x;   // < N_VOX*8
    out[t] = bias4[t & 7];                                  // bias init
    if (t < N_VOX * C_IN / 8) {                             // convert (half grid)
        const float4 a = in4[2 * t];
        const float4 b = in4[2 * t + 1];
        __half2* dst = g_hfeat + 4 * t;
        dst[0] = __floats2half2_rn(a.x, a.y);
        dst[1] = __floats2half2_rn(a.z, a.w);
        dst[2] = __floats2half2_rn(b.x, b.y);
        dst[3] = __floats2half2_rn(b.z, b.w);
    }
}

__device__ __forceinline__ uint32_t pack_h2(float lo, float hi) {
    __half2 h = __floats2half2_rn(lo, hi);
    return *reinterpret_cast<uint32_t*>(&h);
}

// ---------------------------------------------------------------------------
// Kernel 2: cp.async fp16 gather (double buffer) -> ldmatrix -> fp16
// mma.sync (m16n8k16, ALL B frags register-resident) -> D staged to smem
// (conflict-free RSD=40) -> line-coalesced red.global.add.v4 scatter.
// ---------------------------------------------------------------------------
__global__ void __launch_bounds__(TPB, 4)
conv_mma_kernel(const float* __restrict__ kernel_w,     // [K3][32][32]
                const int*   __restrict__ nbmap,        // [M][2] (src,dst)
                float*       __restrict__ out)          // [N_VOX][32]
{
    __shared__ __align__(16) __half As[2][TILE * RSH];  // 2 x 10240B
    __shared__ __align__(16) float  Ds[TILE * RSD];     // 20480B

    const int tid  = threadIdx.x;
    const int wid  = tid >> 5;
    const int lane = tid & 31;

    const int tile0 = blockIdx.x * NT;
    const int k     = tile0 / TILES_PER_K;

    // ---- ALL B fragments in registers (fp16, loaded once per block) ----
    uint32_t Breg[4][2][2];
    {
        const float* wk = kernel_w + (size_t)k * (C_IN * C_OUT);
        const int bk = 2 * (lane & 3), bn = lane >> 2;
#pragma unroll
        for (int j = 0; j < 4; j++)
#pragma unroll
            for (int s = 0; s < 2; s++) {
                const int kb = 16 * s + bk;
                Breg[j][s][0] = pack_h2(wk[(kb    ) * C_OUT + 8 * j + bn],
                                        wk[(kb + 1) * C_OUT + 8 * j + bn]);
                Breg[j][s][1] = pack_h2(wk[(kb + 8) * C_OUT + 8 * j + bn],
                                        wk[(kb + 9) * C_OUT + 8 * j + bn]);
            }
    }

    const __half* hf = reinterpret_cast<const __half*>(g_hfeat);

    // ---- gather tile t into buffer buf: 512 x cp.async.cg 16B ----
    auto gather = [&](int t, int buf) {
        const size_t pbase = (size_t)(tile0 + t) * TILE;
#pragma unroll
        for (int jj = 0; jj < 2; jj++) {
            const int idx = tid + TPB * jj;          // 0..511
            const int ch  = (idx >> 3) & 3;          // 16B chunk in 64B row
            const int row = (idx & 7) + 8 * (idx >> 5);
            const int v   = nbmap[2 * (pbase + row)];
            const uint32_t dst = (uint32_t)__cvta_generic_to_shared(
                &As[buf][row * RSH + ch * 8]);
            asm volatile("cp.async.cg.shared.global [%0], [%1], 16;"
                         :: "r"(dst), "l"(hf + (size_t)v * C_IN + ch * 8));
        }
        asm volatile("cp.async.commit_group;" ::: "memory");
    };

    gather(0, 0);

    const int ar = lane >> 2;                       // frag row-in-8
    const int ac = lane & 3;                        // frag col-pair
    const int lm_row = 16 * wid + (lane & 15);
    const int lm_off = (lane >> 4) * 8;             // halves

    for (int t = 0; t < NT; t++) {
        const int buf = t & 1;
        asm volatile("cp.async.wait_group 0;" ::: "memory");
        __syncthreads();                            // A(t) ready; Ds free

        if (t + 1 < NT) gather(t + 1, buf ^ 1);     // overlap with compute

        // A fragments via 2 x ldmatrix.x4 (one per k16 step).
        uint32_t A[2][4];
        const uint32_t abase = (uint32_t)__cvta_generic_to_shared(
            &As[buf][lm_row * RSH + lm_off]);
#pragma unroll
        for (int s = 0; s < 2; s++) {
            asm volatile("ldmatrix.sync.aligned.m8n8.x4.shared.b16 "
                         "{%0,%1,%2,%3}, [%4];"
                         : "=r"(A[s][0]), "=r"(A[s][1]),
                           "=r"(A[s][2]), "=r"(A[s][3])
                         : "r"(abase + 32 * s));    // +16 halves per k-step
        }

#pragma unroll
        for (int j = 0; j < 4; j++) {
            float D0 = 0.f, D1 = 0.f, D2 = 0.f, D3 = 0.f;
#pragma unroll
            for (int s = 0; s < 2; s++) {
                asm volatile(
                    "mma.sync.aligned.m16n8k16.row.col.f32.f16.f16.f32 "
                    "{%0,%1,%2,%3}, {%4,%5,%6,%7}, {%8,%9}, {%0,%1,%2,%3};"
                    : "+f"(D0), "+f"(D1), "+f"(D2), "+f"(D3)
                    : "r"(A[s][0]), "r"(A[s][1]), "r"(A[s][2]), "r"(A[s][3]),
                      "r"(Breg[j][s][0]), "r"(Breg[j][s][1]));
            }
            // Stage D into Ds (warp-private rows; RSD=40 -> conflict-free).
            *reinterpret_cast<float2*>(
                &Ds[(16 * wid + ar)     * RSD + 2 * ac + 8 * j]) =
                make_float2(D0, D1);
            *reinterpret_cast<float2*>(
                &Ds[(16 * wid + ar + 8) * RSD + 2 * ac + 8 * j]) =
                make_float2(D2, D3);
        }
        __syncwarp();

        // Line-coalesced scatter: lanes 0-7 cover one full 128B output row.
        const size_t pbase = (size_t)(tile0 + t) * TILE;
        const int chunk = lane & 7;
#pragma unroll
        for (int ii = 0; ii < 4; ii++) {
            const int row = 16 * wid + (lane >> 3) + 4 * ii;
            const int y   = nbmap[2 * (pbase + row) + 1];
            const float4 v = *reinterpret_cast<const float4*>(
                &Ds[row * RSD + chunk * 4]);
            asm volatile("red.global.add.v4.f32 [%0], {%1,%2,%3,%4};"
                         :: "l"(out + (size_t)y * C_OUT + chunk * 4),
                            "f"(v.x), "f"(v.y), "f"(v.z), "f"(v.w)
                         : "memory");
        }
        __syncwarp();   // Ds reads done before next tile overwrites
    }
}

// ---------------------------------------------------------------------------
// Inputs (metadata order): in_feature f32[N_VOX,32], kernel f32[27,32,32],
// bias f32[32], nbmap i32[M,2], nbsizes i32[27]. Output f32[N_VOX,32].
// ---------------------------------------------------------------------------
extern "C" void kernel_launch(void* const* d_in, const int* in_sizes, int n_in,
                              void* d_out, int out_size) {
    const float4* in4      = (const float4*)d_in[0];
    const float*  kernel_w = (const float*)d_in[1];
    const float4* bias4    = (const float4*)d_in[2];
    const int*    nbmap    = (const int*)d_in[3];
    float*        out      = (float*)d_out;

    prolog_kernel<<<N_VOX * 8 / 256, 256>>>((float4*)out, bias4, in4);
    conv_mma_kernel<<<GRID, TPB>>>(kernel_w, nbmap, out);
}

// round 15
// speedup vs baseline: 1.0690x; 1.0050x over previous
#include <cuda_runtime.h>
#include <cuda_fp16.h>
#include <cstdint>

#define K3          27
#define PAIRS_PER_K 131072
#define N_VOX       262144
#define C_IN        32
#define C_OUT       32
#define M_TOTAL     (K3 * PAIRS_PER_K)

#define TILE        128                     // pairs per MMA tile (8 warps x 16)
#define NT          8                       // tiles per block (same k)
#define TPB         256
#define TILES_PER_K (PAIRS_PER_K / TILE)    // 1024 (divisible by NT)
#define GRID        (M_TOTAL / TILE / NT)   // 3456
#define RSH         40                      // A row stride in halves (80B)
#define RSD         40                      // D row stride in floats (160B)

// 16MB fp16 copy of in_feature (static device scratch — no allocation).
__device__ __half2 g_hfeat[N_VOX * C_IN / 2];

// ---------------------------------------------------------------------------
// Kernel 1 (fused): bias-init of d_out AND f32->fp16 convert of in_feature.
// ---------------------------------------------------------------------------
__global__ void prolog_kernel(float4* __restrict__ out,
                              const float4* __restrict__ bias4,
                              const float4* __restrict__ in4) {
    const int t = blockIdx.x * blockDim.x + threadIdx.x;   // < N_VOX*8
    out[t] = bias4[t & 7];                                  // bias init
    if (t < N_VOX * C_IN / 8) {                             // convert (half grid)
        const float4 a = in4[2 * t];
        const float4 b = in4[2 * t + 1];
        __half2* dst = g_hfeat + 4 * t;
        dst[0] = __floats2half2_rn(a.x, a.y);
        dst[1] = __floats2half2_rn(a.z, a.w);
        dst[2] = __floats2half2_rn(b.x, b.y);
        dst[3] = __floats2half2_rn(b.z, b.w);
    }
}

__device__ __forceinline__ uint32_t pack_h2(float lo, float hi) {
    __half2 h = __floats2half2_rn(lo, hi);
    return *reinterpret_cast<uint32_t*>(&h);
}

// ---------------------------------------------------------------------------
// Kernel 2: WARP-AUTONOMOUS tiles — zero __syncthreads in the main loop.
// Each warp gathers its own 16 rows (per-warp cp.async groups), runs its
// own fp16 mma.sync, stages D to its private Ds rows, and scatters with
// line-coalesced red.global.add.v4. Warps drift freely across tiles.
// ---------------------------------------------------------------------------
__global__ void __launch_bounds__(TPB, 4)
conv_mma_kernel(const float* __restrict__ kernel_w,     // [K3][32][32]
                const int*   __restrict__ nbmap,        // [M][2] (src,dst)
                float*       __restrict__ out)          // [N_VOX][32]
{
    __shared__ __align__(16) __half As[2][TILE * RSH];  // 2 x 10240B
    __shared__ __align__(16) float  Ds[TILE * RSD];     // 20480B

    const int tid  = threadIdx.x;
    const int wid  = tid >> 5;
    const int lane = tid & 31;

    const int tile0 = blockIdx.x * NT;
    const int k     = tile0 / TILES_PER_K;

    // ---- ALL B fragments in registers (fp16, loaded once per block) ----
    uint32_t Breg[4][2][2];
    {
        const float* wk = kernel_w + (size_t)k * (C_IN * C_OUT);
        const int bk = 2 * (lane & 3), bn = lane >> 2;
#pragma unroll
        for (int j = 0; j < 4; j++)
#pragma unroll
            for (int s = 0; s < 2; s++) {
                const int kb = 16 * s + bk;
                Breg[j][s][0] = pack_h2(wk[(kb    ) * C_OUT + 8 * j + bn],
                                        wk[(kb + 1) * C_OUT + 8 * j + bn]);
                Breg[j][s][1] = pack_h2(wk[(kb + 8) * C_OUT + 8 * j + bn],
                                        wk[(kb + 9) * C_OUT + 8 * j + bn]);
            }
    }

    const __half* hf = reinterpret_cast<const __half*>(g_hfeat);

    // ---- per-warp gather of OWN 16 rows: 64 x cp.async.cg 16B ----
    // lane l: row 16*wid + (l & 15), chunks 2*(l>>4) and 2*(l>>4)+1.
    // Each 8-lane phase hits 8 distinct banks (row stride 80B = 20 words).
    const int g_r16  = lane & 15;
    const int g_ch   = 2 * (lane >> 4);
    auto gatherw = [&](int t, int buf) {
        const size_t pbase = (size_t)(tile0 + t) * TILE + 16 * wid;
        const int v = nbmap[2 * (pbase + g_r16)];
        const __half* src = hf + (size_t)v * C_IN + g_ch * 8;
        const uint32_t dst = (uint32_t)__cvta_generic_to_shared(
            &As[buf][(16 * wid + g_r16) * RSH + g_ch * 8]);
        asm volatile("cp.async.cg.shared.global [%0], [%1], 16;"
                     :: "r"(dst), "l"(src));
        asm volatile("cp.async.cg.shared.global [%0], [%1], 16;"
                     :: "r"(dst + 16), "l"(src + 8));
        asm volatile("cp.async.commit_group;" ::: "memory");
    };

    gatherw(0, 0);

    const int ar = lane >> 2;                       // frag row-in-8
    const int ac = lane & 3;                        // frag col-pair
    const int lm_row = 16 * wid + (lane & 15);
    const int lm_off = (lane >> 4) * 8;             // halves

    for (int t = 0; t < NT; t++) {
        const int buf = t & 1;
        // Prefetch next tile into the other (warp-private) buffer, then wait
        // for the oldest group only. ldmatrix.sync of tile t-1 completed
        // before any lane issued gather(t), so the buffer reuse is safe.
        if (t + 1 < NT) {
            gatherw(t + 1, buf ^ 1);
            asm volatile("cp.async.wait_group 1;" ::: "memory");
        } else {
            asm volatile("cp.async.wait_group 0;" ::: "memory");
        }
        __syncwarp();                               // A(t) visible warp-wide

        // A fragments via 2 x ldmatrix.x4 (one per k16 step).
        uint32_t A[2][4];
        const uint32_t abase = (uint32_t)__cvta_generic_to_shared(
            &As[buf][lm_row * RSH + lm_off]);
#pragma unroll
        for (int s = 0; s < 2; s++) {
            asm volatile("ldmatrix.sync.aligned.m8n8.x4.shared.b16 "
                         "{%0,%1,%2,%3}, [%4];"
                         : "=r"(A[s][0]), "=r"(A[s][1]),
                           "=r"(A[s][2]), "=r"(A[s][3])
                         : "r"(abase + 32 * s));    // +16 halves per k-step
        }

#pragma unroll
        for (int j = 0; j < 4; j++) {
            float D0 = 0.f, D1 = 0.f, D2 = 0.f, D3 = 0.f;
#pragma unroll
            for (int s = 0; s < 2; s++) {
                asm volatile(
                    "mma.sync.aligned.m16n8k16.row.col.f32.f16.f16.f32 "
                    "{%0,%1,%2,%3}, {%4,%5,%6,%7}, {%8,%9}, {%0,%1,%2,%3};"
                    : "+f"(D0), "+f"(D1), "+f"(D2), "+f"(D3)
                    : "r"(A[s][0]), "r"(A[s][1]), "r"(A[s][2]), "r"(A[s][3]),
                      "r"(Breg[j][s][0]), "r"(Breg[j][s][1]));
            }
            // Stage D into Ds (warp-private rows; RSD=40 -> conflict-free).
            *reinterpret_cast<float2*>(
                &Ds[(16 * wid + ar)     * RSD + 2 * ac + 8 * j]) =
                make_float2(D0, D1);
            *reinterpret_cast<float2*>(
                &Ds[(16 * wid + ar + 8) * RSD + 2 * ac + 8 * j]) =
                make_float2(D2, D3);
        }
        __syncwarp();

        // Line-coalesced scatter: lanes 0-7 cover one full 128B output row.
        const size_t pbase = (size_t)(tile0 + t) * TILE;
        const int chunk = lane & 7;
#pragma unroll
        for (int ii = 0; ii < 4; ii++) {
            const int row = 16 * wid + (lane >> 3) + 4 * ii;
            const int y   = nbmap[2 * (pbase + row) + 1];
            const float4 v = *reinterpret_cast<const float4*>(
                &Ds[row * RSD + chunk * 4]);
            asm volatile("red.global.add.v4.f32 [%0], {%1,%2,%3,%4};"
                         :: "l"(out + (size_t)y * C_OUT + chunk * 4),
                            "f"(v.x), "f"(v.y), "f"(v.z), "f"(v.w)
                         : "memory");
        }
        __syncwarp();   // Ds reads done before next tile overwrites
    }
}

// ---------------------------------------------------------------------------
// Inputs (metadata order): in_feature f32[N_VOX,32], kernel f32[27,32,32],
// bias f32[32], nbmap i32[M,2], nbsizes i32[27]. Output f32[N_VOX,32].
// ---------------------------------------------------------------------------
extern "C" void kernel_launch(void* const* d_in, const int* in_sizes, int n_in,
                              void* d_out, int out_size) {
    const float4* in4      = (const float4*)d_in[0];
    const float*  kernel_w = (const float*)d_in[1];
    const float4* bias4    = (const float4*)d_in[2];
    const int*    nbmap    = (const int*)d_in[3];
    float*        out      = (float*)d_out;

    prolog_kernel<<<N_VOX * 8 / 256, 256>>>((float4*)out, bias4, in4);
    conv_mma_kernel<<<GRID, TPB>>>(kernel_w, nbmap, out);
}